// round 2
// baseline (speedup 1.0000x reference)
#include <cuda_runtime.h>
#include <math.h>

// Problem constants (fixed by the dataset)
#define Nn 100000
#define Ee 1600000
#define NCc 10000
#define Gg 1000
#define ND 32
#define ED 8
#define NLAYERS 4

// Scratch state (no cudaMalloc allowed). Zero-initialized at module load.
__device__ __align__(16) float g_h[(size_t)Nn * ND];     // 12.8 MB
__device__ __align__(16) float g_e[(size_t)Ee * ED];     // 51.2 MB
__device__ __align__(16) float g_agg[(size_t)Nn * ED];   // 3.2 MB (self-clearing)
__device__ float g_logits[NCc];
__device__ int   g_seg[NCc];
__device__ float g_gmax[Gg];
__device__ float g_gsum[Gg];

// ---------------------------------------------------------------------------
// h = x @ Wn_in + bn_in
__global__ __launch_bounds__(256) void k_init_h(const float* __restrict__ x,
                                                const float* __restrict__ Wn_in,
                                                const float* __restrict__ bn_in) {
    int n = blockIdx.x * blockDim.x + threadIdx.x;
    if (n >= Nn) return;
    float x0 = x[2 * n], x1 = x[2 * n + 1];
#pragma unroll
    for (int j = 0; j < ND; j++)
        g_h[(size_t)n * ND + j] = fmaf(x0, Wn_in[j], fmaf(x1, Wn_in[ND + j], bn_in[j]));
}

// e = edge_attr @ We_in + be_in
__global__ __launch_bounds__(256) void k_init_e(const float* __restrict__ edge_attr,
                                                const float* __restrict__ We_in,
                                                const float* __restrict__ be_in) {
    int i = blockIdx.x * blockDim.x + threadIdx.x;
    if (i >= Ee) return;
    float a = edge_attr[i];
#pragma unroll
    for (int j = 0; j < ED; j++)
        g_e[(size_t)i * ED + j] = fmaf(a, We_in[j], be_in[j]);
}

__global__ void k_ginit() {
    int g = blockIdx.x * blockDim.x + threadIdx.x;
    if (g >= Gg) return;
    g_gmax[g] = -INFINITY;
    g_gsum[g] = 0.f;
}

// ---------------------------------------------------------------------------
// Edge update: new_e = relu([h_src, h_dst, e] @ We + be); e += new_e;
// agg[dst] += new_e (vector reduction, no return).
__global__ __launch_bounds__(256) void k_edge(const int* __restrict__ src,
                                              const int* __restrict__ dst,
                                              const float* __restrict__ We,   // [72,8]
                                              const float* __restrict__ be) { // [8]
    __shared__ float sW[(2 * ND + ED) * ED];  // 576
    __shared__ float sb[ED];
    for (int i = threadIdx.x; i < (2 * ND + ED) * ED; i += blockDim.x) sW[i] = We[i];
    if (threadIdx.x < ED) sb[threadIdx.x] = be[threadIdx.x];
    __syncthreads();

    int eid = blockIdx.x * blockDim.x + threadIdx.x;
    if (eid >= Ee) return;
    int s = src[eid], d = dst[eid];

    float acc[ED];
#pragma unroll
    for (int j = 0; j < ED; j++) acc[j] = sb[j];

    const float4* hs = reinterpret_cast<const float4*>(g_h + (size_t)s * ND);
#pragma unroll
    for (int q = 0; q < ND / 4; q++) {
        float4 v = hs[q];
        float m[4] = {v.x, v.y, v.z, v.w};
#pragma unroll
        for (int c = 0; c < 4; c++) {
            const float* w = &sW[(q * 4 + c) * ED];
#pragma unroll
            for (int j = 0; j < ED; j++) acc[j] = fmaf(m[c], w[j], acc[j]);
        }
    }
    const float4* hd = reinterpret_cast<const float4*>(g_h + (size_t)d * ND);
#pragma unroll
    for (int q = 0; q < ND / 4; q++) {
        float4 v = hd[q];
        float m[4] = {v.x, v.y, v.z, v.w};
#pragma unroll
        for (int c = 0; c < 4; c++) {
            const float* w = &sW[(ND + q * 4 + c) * ED];
#pragma unroll
            for (int j = 0; j < ED; j++) acc[j] = fmaf(m[c], w[j], acc[j]);
        }
    }
    float4* ep = reinterpret_cast<float4*>(g_e + (size_t)eid * ED);
    float4 e0 = ep[0], e1 = ep[1];
    float ev[ED] = {e0.x, e0.y, e0.z, e0.w, e1.x, e1.y, e1.z, e1.w};
#pragma unroll
    for (int k = 0; k < ED; k++) {
        const float* w = &sW[(2 * ND + k) * ED];
#pragma unroll
        for (int j = 0; j < ED; j++) acc[j] = fmaf(ev[k], w[j], acc[j]);
    }

    float ne[ED];
#pragma unroll
    for (int j = 0; j < ED; j++) ne[j] = fmaxf(acc[j], 0.f);

    // residual e update
    ep[0] = make_float4(e0.x + ne[0], e0.y + ne[1], e0.z + ne[2], e0.w + ne[3]);
    ep[1] = make_float4(e1.x + ne[4], e1.y + ne[5], e1.z + ne[6], e1.w + ne[7]);

    // scatter-add new_e into agg[dst] via vector reduction (no return)
    float* ap = g_agg + (size_t)d * ED;
    asm volatile("red.global.add.v4.f32 [%0], {%1,%2,%3,%4};"
                 :: "l"(ap), "f"(ne[0]), "f"(ne[1]), "f"(ne[2]), "f"(ne[3]) : "memory");
    asm volatile("red.global.add.v4.f32 [%0], {%1,%2,%3,%4};"
                 :: "l"(ap + 4), "f"(ne[4]), "f"(ne[5]), "f"(ne[6]), "f"(ne[7]) : "memory");
}

// ---------------------------------------------------------------------------
// Node update: h += relu([h, agg] @ Wn + bn); clears agg for next layer.
__global__ __launch_bounds__(256) void k_node(const float* __restrict__ Wn,   // [40,32]
                                              const float* __restrict__ bn) { // [32]
    __shared__ float sW[(ND + ED) * ND];  // 1280
    __shared__ float sb[ND];
    for (int i = threadIdx.x; i < (ND + ED) * ND; i += blockDim.x) sW[i] = Wn[i];
    if (threadIdx.x < ND) sb[threadIdx.x] = bn[threadIdx.x];
    __syncthreads();

    int n = blockIdx.x * blockDim.x + threadIdx.x;
    if (n >= Nn) return;

    float acc[ND];
#pragma unroll
    for (int j = 0; j < ND; j++) acc[j] = sb[j];

    float4* hp = reinterpret_cast<float4*>(g_h + (size_t)n * ND);
    float4 hq[ND / 4];
#pragma unroll
    for (int q = 0; q < ND / 4; q++) {
        hq[q] = hp[q];
        float m[4] = {hq[q].x, hq[q].y, hq[q].z, hq[q].w};
#pragma unroll
        for (int c = 0; c < 4; c++) {
            const float* w = &sW[(q * 4 + c) * ND];
#pragma unroll
            for (int j = 0; j < ND; j++) acc[j] = fmaf(m[c], w[j], acc[j]);
        }
    }
    float4* ap = reinterpret_cast<float4*>(g_agg + (size_t)n * ED);
    float4 a0 = ap[0], a1 = ap[1];
    // clear agg for next layer (keeps state deterministic across calls)
    ap[0] = make_float4(0.f, 0.f, 0.f, 0.f);
    ap[1] = make_float4(0.f, 0.f, 0.f, 0.f);
    float av[ED] = {a0.x, a0.y, a0.z, a0.w, a1.x, a1.y, a1.z, a1.w};
#pragma unroll
    for (int k = 0; k < ED; k++) {
        const float* w = &sW[(ND + k) * ND];
#pragma unroll
        for (int j = 0; j < ND; j++) acc[j] = fmaf(av[k], w[j], acc[j]);
    }

    float hv[ND] = {hq[0].x, hq[0].y, hq[0].z, hq[0].w, hq[1].x, hq[1].y, hq[1].z, hq[1].w,
                    hq[2].x, hq[2].y, hq[2].z, hq[2].w, hq[3].x, hq[3].y, hq[3].z, hq[3].w,
                    hq[4].x, hq[4].y, hq[4].z, hq[4].w, hq[5].x, hq[5].y, hq[5].z, hq[5].w,
                    hq[6].x, hq[6].y, hq[6].z, hq[6].w, hq[7].x, hq[7].y, hq[7].z, hq[7].w};
    float out[ND];
#pragma unroll
    for (int j = 0; j < ND; j++) out[j] = hv[j] + fmaxf(acc[j], 0.f);
#pragma unroll
    for (int q = 0; q < ND / 4; q++)
        hp[q] = make_float4(out[q * 4], out[q * 4 + 1], out[q * 4 + 2], out[q * 4 + 3]);
}

// ---------------------------------------------------------------------------
__device__ __forceinline__ void atomicMaxFloat(float* addr, float v) {
    if (v >= 0.f)
        atomicMax(reinterpret_cast<int*>(addr), __float_as_int(v));
    else
        atomicMin(reinterpret_cast<unsigned int*>(addr), __float_as_uint(v));
}

__global__ __launch_bounds__(256) void k_logits(const int* __restrict__ cand,
                                                const int* __restrict__ batch,
                                                const float* __restrict__ Wout, // [32]
                                                const float* __restrict__ bout) {
    int i = blockIdx.x * blockDim.x + threadIdx.x;
    if (i >= NCc) return;
    int c = cand[i];
    const float4* hp = reinterpret_cast<const float4*>(g_h + (size_t)c * ND);
    const float4* wp = reinterpret_cast<const float4*>(Wout);
    float acc = bout[0];
#pragma unroll
    for (int q = 0; q < ND / 4; q++) {
        float4 v = hp[q];
        float4 w = wp[q];
        acc = fmaf(v.x, w.x, acc);
        acc = fmaf(v.y, w.y, acc);
        acc = fmaf(v.z, w.z, acc);
        acc = fmaf(v.w, w.w, acc);
    }
    g_logits[i] = acc;
    int sg = batch[c];
    g_seg[i] = sg;
    atomicMaxFloat(&g_gmax[sg], acc);
}

__global__ __launch_bounds__(256) void k_expsum() {
    int i = blockIdx.x * blockDim.x + threadIdx.x;
    if (i >= NCc) return;
    int sg = g_seg[i];
    atomicAdd(&g_gsum[sg], expf(g_logits[i] - g_gmax[sg]));
}

__global__ __launch_bounds__(256) void k_final(float* __restrict__ out) {
    int i = blockIdx.x * blockDim.x + threadIdx.x;
    if (i >= NCc) return;
    int sg = g_seg[i];
    out[i] = g_logits[i] - g_gmax[sg] - logf(g_gsum[sg]);
}

// ---------------------------------------------------------------------------
extern "C" void kernel_launch(void* const* d_in, const int* in_sizes, int n_in,
                              void* d_out, int out_size) {
    const float* x         = (const float*)d_in[0];
    const float* edge_attr = (const float*)d_in[1];
    const float* Wn_in     = (const float*)d_in[2];
    const float* bn_in     = (const float*)d_in[3];
    const float* We_in     = (const float*)d_in[4];
    const float* be_in     = (const float*)d_in[5];
    const float* We_l      = (const float*)d_in[6];   // [4,72,8]
    const float* be_l      = (const float*)d_in[7];   // [4,8]
    const float* Wn_l      = (const float*)d_in[8];   // [4,40,32]
    const float* bn_l      = (const float*)d_in[9];   // [4,32]
    const float* Wout      = (const float*)d_in[10];  // [32,1]
    const float* bout      = (const float*)d_in[11];  // [1]
    const int*   edge_index = (const int*)d_in[12];   // [2,E]
    const int*   batch      = (const int*)d_in[13];   // [N]
    const int*   cand       = (const int*)d_in[14];   // [NC]
    float* out = (float*)d_out;

    const int* src = edge_index;
    const int* dst = edge_index + Ee;

    k_init_h<<<(Nn + 255) / 256, 256>>>(x, Wn_in, bn_in);
    k_init_e<<<(Ee + 255) / 256, 256>>>(edge_attr, We_in, be_in);
    k_ginit<<<(Gg + 255) / 256, 256>>>();

    for (int l = 0; l < NLAYERS; l++) {
        k_edge<<<(Ee + 255) / 256, 256>>>(src, dst,
                                          We_l + (size_t)l * (2 * ND + ED) * ED,
                                          be_l + (size_t)l * ED);
        k_node<<<(Nn + 255) / 256, 256>>>(Wn_l + (size_t)l * (ND + ED) * ND,
                                          bn_l + (size_t)l * ND);
    }

    k_logits<<<(NCc + 255) / 256, 256>>>(cand, batch, Wout, bout);
    k_expsum<<<(NCc + 255) / 256, 256>>>();
    k_final<<<(NCc + 255) / 256, 256>>>(out);
}

// round 5
// speedup vs baseline: 2.4870x; 2.4870x over previous
#include <cuda_runtime.h>
#include <math.h>

#define Nn 100000
#define Ee 1600000
#define NCc 10000
#define Gg 1000
#define ND 32
#define ED 8
#define NLAYERS 4

// Scratch state (no cudaMalloc allowed).
__device__ __align__(16) float g_h[(size_t)Nn * ND];     // 12.8 MB
__device__ __align__(16) float g_e[(size_t)Ee * ED];     // 51.2 MB
__device__ __align__(16) float g_agg[(size_t)Nn * ED];   // 3.2 MB (self-clearing)
__device__ __align__(16) float g_A[(size_t)Nn * ED];     // h @ We_l[l][0:32]
__device__ __align__(16) float g_B[(size_t)Nn * ED];     // h @ We_l[l][32:64]
__device__ float g_logits[NCc];
__device__ int   g_seg[NCc];
__device__ float g_gmax[Gg];
__device__ float g_gsum[Gg];

// ---------------------------------------------------------------------------
// h = x @ Wn_in + bn_in ; A,B = h @ We_l[0] partials (for the first edge pass)
__global__ __launch_bounds__(256) void k_init_h(const float* __restrict__ x,
                                                const float* __restrict__ Wn_in,  // [2,32]
                                                const float* __restrict__ bn_in,  // [32]
                                                const float* __restrict__ Wab) {  // We_l[0], first 64 rows x 8
    __shared__ float sWn[2 * ND];
    __shared__ float sbn[ND];
    __shared__ float sWab[64 * ED];   // rows 0..63 of We_l[0]
    for (int i = threadIdx.x; i < 2 * ND; i += blockDim.x) sWn[i] = Wn_in[i];
    for (int i = threadIdx.x; i < ND; i += blockDim.x) sbn[i] = bn_in[i];
    for (int i = threadIdx.x; i < 64 * ED; i += blockDim.x) sWab[i] = Wab[i];
    __syncthreads();

    int n = blockIdx.x * blockDim.x + threadIdx.x;
    if (n >= Nn) return;
    float x0 = x[2 * n], x1 = x[2 * n + 1];
    float hv[ND];
#pragma unroll
    for (int j = 0; j < ND; j++)
        hv[j] = fmaf(x0, sWn[j], fmaf(x1, sWn[ND + j], sbn[j]));

    float4* hp = reinterpret_cast<float4*>(g_h + (size_t)n * ND);
#pragma unroll
    for (int q = 0; q < ND / 4; q++)
        hp[q] = make_float4(hv[4 * q], hv[4 * q + 1], hv[4 * q + 2], hv[4 * q + 3]);

    float av[ED], bv[ED];
#pragma unroll
    for (int j = 0; j < ED; j++) { av[j] = 0.f; bv[j] = 0.f; }
#pragma unroll
    for (int c = 0; c < ND; c++) {
        float m = hv[c];
#pragma unroll
        for (int j = 0; j < ED; j++) {
            av[j] = fmaf(m, sWab[c * ED + j], av[j]);
            bv[j] = fmaf(m, sWab[(ND + c) * ED + j], bv[j]);
        }
    }
    float4* Ap = reinterpret_cast<float4*>(g_A + (size_t)n * ED);
    float4* Bp = reinterpret_cast<float4*>(g_B + (size_t)n * ED);
    Ap[0] = make_float4(av[0], av[1], av[2], av[3]);
    Ap[1] = make_float4(av[4], av[5], av[6], av[7]);
    Bp[0] = make_float4(bv[0], bv[1], bv[2], bv[3]);
    Bp[1] = make_float4(bv[4], bv[5], bv[6], bv[7]);
}

__global__ void k_ginit() {
    int g = blockIdx.x * blockDim.x + threadIdx.x;
    if (g >= Gg) return;
    g_gmax[g] = -INFINITY;
    g_gsum[g] = 0.f;
}

// ---------------------------------------------------------------------------
// Shared body of the edge pass, given this edge's current e in ev[8].
// W3 (8x8) and bias are in registers.
__device__ __forceinline__ void edge_body(int eid, int s, int d,
                                          const float* __restrict__ w3,  // [64] regs
                                          const float* __restrict__ bl,  // [8] regs
                                          const float ev[ED]) {
    const float4* Ap = reinterpret_cast<const float4*>(g_A + (size_t)s * ED);
    const float4* Bp = reinterpret_cast<const float4*>(g_B + (size_t)d * ED);
    float4 a0 = Ap[0], a1 = Ap[1];
    float4 b0 = Bp[0], b1 = Bp[1];
    float acc[ED] = {a0.x + b0.x + bl[0], a0.y + b0.y + bl[1],
                     a0.z + b0.z + bl[2], a0.w + b0.w + bl[3],
                     a1.x + b1.x + bl[4], a1.y + b1.y + bl[5],
                     a1.z + b1.z + bl[6], a1.w + b1.w + bl[7]};
#pragma unroll
    for (int k = 0; k < ED; k++) {
        float m = ev[k];
#pragma unroll
        for (int j = 0; j < ED; j++) acc[j] = fmaf(m, w3[k * ED + j], acc[j]);
    }
    float ne[ED];
#pragma unroll
    for (int j = 0; j < ED; j++) ne[j] = fmaxf(acc[j], 0.f);

    float4* ep = reinterpret_cast<float4*>(g_e + (size_t)eid * ED);
    ep[0] = make_float4(ev[0] + ne[0], ev[1] + ne[1], ev[2] + ne[2], ev[3] + ne[3]);
    ep[1] = make_float4(ev[4] + ne[4], ev[5] + ne[5], ev[6] + ne[6], ev[7] + ne[7]);

    float* ap = g_agg + (size_t)d * ED;
    asm volatile("red.global.add.v4.f32 [%0], {%1,%2,%3,%4};"
                 :: "l"(ap), "f"(ne[0]), "f"(ne[1]), "f"(ne[2]), "f"(ne[3]) : "memory");
    asm volatile("red.global.add.v4.f32 [%0], {%1,%2,%3,%4};"
                 :: "l"(ap + 4), "f"(ne[4]), "f"(ne[5]), "f"(ne[6]), "f"(ne[7]) : "memory");
}

// Layer 0: fuses e initialization (e0 = a*We_in + be_in) — g_e never pre-written.
__global__ __launch_bounds__(128) void k_edge0(const int* __restrict__ src,
                                               const int* __restrict__ dst,
                                               const float* __restrict__ edge_attr,
                                               const float* __restrict__ W3g,  // We_l[0]+64*8
                                               const float* __restrict__ blg,  // be_l[0]
                                               const float* __restrict__ Weing,
                                               const float* __restrict__ being) {
    float w3[64];
#pragma unroll
    for (int i = 0; i < 16; i++)
        reinterpret_cast<float4*>(w3)[i] = reinterpret_cast<const float4*>(W3g)[i];
    float bl[ED], wei[ED], bei[ED];
#pragma unroll
    for (int j = 0; j < ED; j++) { bl[j] = blg[j]; wei[j] = Weing[j]; bei[j] = being[j]; }

    int stride = gridDim.x * blockDim.x;
#pragma unroll 2
    for (int eid = blockIdx.x * blockDim.x + threadIdx.x; eid < Ee; eid += stride) {
        int s = src[eid], d = dst[eid];
        float a = edge_attr[eid];
        float ev[ED];
#pragma unroll
        for (int j = 0; j < ED; j++) ev[j] = fmaf(a, wei[j], bei[j]);
        edge_body(eid, s, d, w3, bl, ev);
    }
}

// Layers 1..3: e read from g_e.
__global__ __launch_bounds__(128) void k_edge(const int* __restrict__ src,
                                              const int* __restrict__ dst,
                                              const float* __restrict__ W3g,
                                              const float* __restrict__ blg) {
    float w3[64];
#pragma unroll
    for (int i = 0; i < 16; i++)
        reinterpret_cast<float4*>(w3)[i] = reinterpret_cast<const float4*>(W3g)[i];
    float bl[ED];
#pragma unroll
    for (int j = 0; j < ED; j++) bl[j] = blg[j];

    int stride = gridDim.x * blockDim.x;
#pragma unroll 2
    for (int eid = blockIdx.x * blockDim.x + threadIdx.x; eid < Ee; eid += stride) {
        int s = src[eid], d = dst[eid];
        const float4* ep = reinterpret_cast<const float4*>(g_e + (size_t)eid * ED);
        float4 e0 = ep[0], e1 = ep[1];
        float ev[ED] = {e0.x, e0.y, e0.z, e0.w, e1.x, e1.y, e1.z, e1.w};
        edge_body(eid, s, d, w3, bl, ev);
    }
}

// ---------------------------------------------------------------------------
// Node update: h += relu([h, agg] @ Wn + bn); clears agg; computes next layer's
// A,B partials from the updated h (Wab = We_l[l+1] rows 0..63, or null).
__global__ __launch_bounds__(256) void k_node(const float* __restrict__ Wn,   // [40,32]
                                              const float* __restrict__ bn,   // [32]
                                              const float* __restrict__ Wab) {
    __shared__ float sW[(ND + ED) * ND];  // 1280
    __shared__ float sb[ND];
    __shared__ float sWab[64 * ED];       // 512
    for (int i = threadIdx.x; i < (ND + ED) * ND; i += blockDim.x) sW[i] = Wn[i];
    if (threadIdx.x < ND) sb[threadIdx.x] = bn[threadIdx.x];
    if (Wab)
        for (int i = threadIdx.x; i < 64 * ED; i += blockDim.x) sWab[i] = Wab[i];
    __syncthreads();

    int n = blockIdx.x * blockDim.x + threadIdx.x;
    if (n >= Nn) return;

    float acc[ND];
#pragma unroll
    for (int j = 0; j < ND; j++) acc[j] = sb[j];

    float4* hp = reinterpret_cast<float4*>(g_h + (size_t)n * ND);
    float hv[ND];
#pragma unroll
    for (int q = 0; q < ND / 4; q++) {
        float4 v = hp[q];
        hv[4 * q] = v.x; hv[4 * q + 1] = v.y; hv[4 * q + 2] = v.z; hv[4 * q + 3] = v.w;
    }
#pragma unroll
    for (int c = 0; c < ND; c++) {
        float m = hv[c];
#pragma unroll
        for (int j = 0; j < ND; j++) acc[j] = fmaf(m, sW[c * ND + j], acc[j]);
    }
    float4* ap = reinterpret_cast<float4*>(g_agg + (size_t)n * ED);
    float4 a0 = ap[0], a1 = ap[1];
    ap[0] = make_float4(0.f, 0.f, 0.f, 0.f);   // clear for next layer
    ap[1] = make_float4(0.f, 0.f, 0.f, 0.f);
    float av[ED] = {a0.x, a0.y, a0.z, a0.w, a1.x, a1.y, a1.z, a1.w};
#pragma unroll
    for (int k = 0; k < ED; k++) {
        float m = av[k];
#pragma unroll
        for (int j = 0; j < ND; j++) acc[j] = fmaf(m, sW[(ND + k) * ND + j], acc[j]);
    }

    float out[ND];
#pragma unroll
    for (int j = 0; j < ND; j++) out[j] = hv[j] + fmaxf(acc[j], 0.f);
#pragma unroll
    for (int q = 0; q < ND / 4; q++)
        hp[q] = make_float4(out[4 * q], out[4 * q + 1], out[4 * q + 2], out[4 * q + 3]);

    if (Wab) {
        float pa[ED], pb[ED];
#pragma unroll
        for (int j = 0; j < ED; j++) { pa[j] = 0.f; pb[j] = 0.f; }
#pragma unroll
        for (int c = 0; c < ND; c++) {
            float m = out[c];
#pragma unroll
            for (int j = 0; j < ED; j++) {
                pa[j] = fmaf(m, sWab[c * ED + j], pa[j]);
                pb[j] = fmaf(m, sWab[(ND + c) * ED + j], pb[j]);
            }
        }
        float4* Ap = reinterpret_cast<float4*>(g_A + (size_t)n * ED);
        float4* Bp = reinterpret_cast<float4*>(g_B + (size_t)n * ED);
        Ap[0] = make_float4(pa[0], pa[1], pa[2], pa[3]);
        Ap[1] = make_float4(pa[4], pa[5], pa[6], pa[7]);
        Bp[0] = make_float4(pb[0], pb[1], pb[2], pb[3]);
        Bp[1] = make_float4(pb[4], pb[5], pb[6], pb[7]);
    }
}

// ---------------------------------------------------------------------------
__device__ __forceinline__ void atomicMaxFloat(float* addr, float v) {
    if (v >= 0.f)
        atomicMax(reinterpret_cast<int*>(addr), __float_as_int(v));
    else
        atomicMin(reinterpret_cast<unsigned int*>(addr), __float_as_uint(v));
}

__global__ __launch_bounds__(256) void k_logits(const int* __restrict__ cand,
                                                const int* __restrict__ batch,
                                                const float* __restrict__ Wout,
                                                const float* __restrict__ bout) {
    int i = blockIdx.x * blockDim.x + threadIdx.x;
    if (i >= NCc) return;
    int c = cand[i];
    const float4* hp = reinterpret_cast<const float4*>(g_h + (size_t)c * ND);
    const float4* wp = reinterpret_cast<const float4*>(Wout);
    float acc = bout[0];
#pragma unroll
    for (int q = 0; q < ND / 4; q++) {
        float4 v = hp[q];
        float4 w = wp[q];
        acc = fmaf(v.x, w.x, acc);
        acc = fmaf(v.y, w.y, acc);
        acc = fmaf(v.z, w.z, acc);
        acc = fmaf(v.w, w.w, acc);
    }
    g_logits[i] = acc;
    int sg = batch[c];
    g_seg[i] = sg;
    atomicMaxFloat(&g_gmax[sg], acc);
}

__global__ __launch_bounds__(256) void k_expsum() {
    int i = blockIdx.x * blockDim.x + threadIdx.x;
    if (i >= NCc) return;
    int sg = g_seg[i];
    atomicAdd(&g_gsum[sg], expf(g_logits[i] - g_gmax[sg]));
}

__global__ __launch_bounds__(256) void k_final(float* __restrict__ out) {
    int i = blockIdx.x * blockDim.x + threadIdx.x;
    if (i >= NCc) return;
    int sg = g_seg[i];
    out[i] = g_logits[i] - g_gmax[sg] - logf(g_gsum[sg]);
}

// ---------------------------------------------------------------------------
extern "C" void kernel_launch(void* const* d_in, const int* in_sizes, int n_in,
                              void* d_out, int out_size) {
    const float* x         = (const float*)d_in[0];
    const float* edge_attr = (const float*)d_in[1];
    const float* Wn_in     = (const float*)d_in[2];
    const float* bn_in     = (const float*)d_in[3];
    const float* We_in     = (const float*)d_in[4];
    const float* be_in     = (const float*)d_in[5];
    const float* We_l      = (const float*)d_in[6];   // [4,72,8]
    const float* be_l      = (const float*)d_in[7];   // [4,8]
    const float* Wn_l      = (const float*)d_in[8];   // [4,40,32]
    const float* bn_l      = (const float*)d_in[9];   // [4,32]
    const float* Wout      = (const float*)d_in[10];  // [32,1]
    const float* bout      = (const float*)d_in[11];  // [1]
    const int*   edge_index = (const int*)d_in[12];   // [2,E]
    const int*   batch      = (const int*)d_in[13];   // [N]
    const int*   cand       = (const int*)d_in[14];   // [NC]
    float* out = (float*)d_out;

    const int* src = edge_index;
    const int* dst = edge_index + Ee;

    const int EBLK = 1184;   // 148 SMs * 8, grid-stride

    k_init_h<<<(Nn + 255) / 256, 256>>>(x, Wn_in, bn_in, We_l);
    k_ginit<<<(Gg + 255) / 256, 256>>>();

    for (int l = 0; l < NLAYERS; l++) {
        const float* W3 = We_l + (size_t)l * 72 * ED + 64 * ED;
        const float* bl = be_l + (size_t)l * ED;
        if (l == 0)
            k_edge0<<<EBLK, 128>>>(src, dst, edge_attr, W3, bl, We_in, be_in);
        else
            k_edge<<<EBLK, 128>>>(src, dst, W3, bl);
        const float* Wab_next = (l + 1 < NLAYERS) ? (We_l + (size_t)(l + 1) * 72 * ED)
                                                  : nullptr;
        k_node<<<(Nn + 255) / 256, 256>>>(Wn_l + (size_t)l * (ND + ED) * ND,
                                          bn_l + (size_t)l * ND, Wab_next);
    }

    k_logits<<<(NCc + 255) / 256, 256>>>(cand, batch, Wout, bout);
    k_expsum<<<(NCc + 255) / 256, 256>>>();
    k_final<<<(NCc + 255) / 256, 256>>>(out);
}